// round 3
// baseline (speedup 1.0000x reference)
#include <cuda_runtime.h>
#include <cstdint>

// ---------------------------------------------------------------------------
// Sinkhorn-Knopp, 65536 independent 32x32 fp32 matrices, 10 iterations.
//
// M after k normalizations == diag(u) * M0 * diag(v)  -> iterate only u, v:
//   d_i = sum_j M0[i][j] v_j ;  u_i <- u_i / (u_i d_i + eps)
//   c_j = sum_i M0[i][j] u_i ;  v_j <- v_j / (v_j c_j + eps)
//
// TWO matrices per warp (lanes 0-15 / 16-31), each matrix on a 4x4 lane grid
// (a = (lane>>2)&3 row-group, b = lane&3 col-group); a lane owns an 8x8
// subtile as 32 f32x2 registers. Every SHFL serves both matrices at once.
//
// xor-slot layout: lane (a,b) stores row-pair slot p = actual row pair b^p
// (rows 8a+2(b^p)+e) and col-pair slot j = actual col pair a^j (cols
// 8b+2(a^j)+f). With this placement, both the cross-lane reductions and the
// u/v allgathers are plain shfl_xor butterflies with NO select/routing
// instructions and NO indexed gathers: the permutation is absorbed into
// which register each value is loaded into (static per lane).
// Per iteration, per warp (= 2 matrices): 24 SHFL total.
// ---------------------------------------------------------------------------

#define FMA2(d, a, b, c) \
    asm("fma.rn.f32x2 %0, %1, %2, %3;" : "=l"(d) : "l"(a), "l"(b), "l"(c))
#define MUL2(d, a, b) \
    asm("mul.rn.f32x2 %0, %1, %2;" : "=l"(d) : "l"(a), "l"(b))
#define ADD2(d, a, b) \
    asm("add.rn.f32x2 %0, %1, %2;" : "=l"(d) : "l"(a), "l"(b))
#define PACK2(d, lo, hi) \
    asm("mov.b64 %0, {%1, %2};" : "=l"(d) : "f"(lo), "f"(hi))
#define UNPACK2(lo, hi, s) \
    asm("mov.b64 {%0, %1}, %2;" : "=f"(lo), "=f"(hi) : "l"(s))
#define RCPA(d, s) \
    asm("rcp.approx.f32 %0, %1;" : "=f"(d) : "f"(s))

using ull = unsigned long long;

static constexpr float    EPS   = 1e-8f;
static constexpr float    SCALE = 14.4269504088896340736f;  // 10 * log2(e)
static constexpr int      WPB   = 4;                        // warps per block
static constexpr unsigned FULL  = 0xFFFFFFFFu;

__global__ __launch_bounds__(WPB * 32, 4)
void sinkhorn_kernel(const float* __restrict__ H,
                     float* __restrict__ Out,
                     int nmat) {
    const int lane = threadIdx.x & 31;
    const int wid  = threadIdx.x >> 5;
    const int h    = lane >> 4;          // which matrix of the pair
    const int a    = (lane >> 2) & 3;    // row group: rows [8a, 8a+8)
    const int b    = lane & 3;           // col group: cols [8b, 8b+8)
    const int ah   = a >> 1;
    const int al   = a & 1;

    int m = (blockIdx.x * WPB + wid) * 2 + h;
    if (m >= nmat) m = nmat - 1;         // duplicate work; identical writes

    const float4* src = reinterpret_cast<const float4*>(H)  + (size_t)m * 256;
    float4*       dst = reinterpret_cast<float4*>(Out)      + (size_t)m * 256;

    ull EPS2; PACK2(EPS2, EPS, EPS);
    ull ONE2; PACK2(ONE2, 1.0f, 1.0f);

    // ---- Load + exp + clamp into xor-slot register layout ----
    // M[i2][j]: i2 = 2p+e -> actual row 8a + 2*(b^p) + e
    //           j          -> actual col pair a^j: cols 8b+2*(a^j), +1
    ull M[8][4];
#pragma unroll
    for (int p = 0; p < 4; p++) {
#pragma unroll
        for (int e = 0; e < 2; e++) {
            const int i2  = 2 * p + e;
            const int row = 8 * a + 2 * (b ^ p) + e;
#pragma unroll
            for (int q = 0; q < 2; q++) {          // q covers slots 2q, 2q+1
                float4 t = src[row * 8 + 2 * b + (ah ^ q)];
                t.x = fmaxf(exp2f(t.x * SCALE), EPS);
                t.y = fmaxf(exp2f(t.y * SCALE), EPS);
                t.z = fmaxf(exp2f(t.z * SCALE), EPS);
                t.w = fmaxf(exp2f(t.w * SCALE), EPS);
                ull lo, hi;
                PACK2(lo, t.x, t.y);
                PACK2(hi, t.z, t.w);
                // slot 2q holds pair with (pair&1)==al ; 2q+1 the other
                M[i2][2 * q + 0] = al ? hi : lo;
                M[i2][2 * q + 1] = al ? lo : hi;
            }
        }
    }

    // u_own: u-pair for rows 8a+2b, 8a+2b+1 ; v_own: v-pair for cols 8b+2a,+1
    ull u_own = ONE2, v_own = ONE2;
    ull V[4];
    V[0] = ONE2; V[1] = ONE2; V[2] = ONE2; V[3] = ONE2;
    ull U[4];

#pragma unroll 1
    for (int it = 0; it < 10; it++) {
        // ================= Row step =====================================
        ull D[4];
#pragma unroll
        for (int p = 0; p < 4; p++) {
            float s[2];
#pragma unroll
            for (int e = 0; e < 2; e++) {
                const int i2 = 2 * p + e;
                ull acc;
                MUL2(acc, M[i2][0], V[0]);
                FMA2(acc, M[i2][1], V[1], acc);
                FMA2(acc, M[i2][2], V[2], acc);
                FMA2(acc, M[i2][3], V[3], acc);
                float lo, hi; UNPACK2(lo, hi, acc);
                s[e] = lo + hi;
            }
            PACK2(D[p], s[0], s[1]);     // partial d-pair for actual pair b^p
        }
        // reduce over b-dim: masks 2 then 1 (pure xor, no routing selects)
        {
            ull r;
            r = __shfl_xor_sync(FULL, D[2], 2); ADD2(D[0], D[0], r);
            r = __shfl_xor_sync(FULL, D[3], 2); ADD2(D[1], D[1], r);
            r = __shfl_xor_sync(FULL, D[1], 1); ADD2(D[0], D[0], r);
        }
        // u update: u <- u / (u*d + eps)   (elementwise on the pair)
        {
            ull t; FMA2(t, u_own, D[0], EPS2);
            float tl, th; UNPACK2(tl, th, t);
            float rl, rh; RCPA(rl, tl); RCPA(rh, th);
            ull rp; PACK2(rp, rl, rh);
            MUL2(u_own, u_own, rp);
        }
        // u allgather over b-dim: U[p] = u-pair for actual pair b^p
        U[0] = u_own;
        U[1] = __shfl_xor_sync(FULL, u_own, 1);
        U[2] = __shfl_xor_sync(FULL, u_own, 2);
        U[3] = __shfl_xor_sync(FULL, u_own, 3);

        // ================= Col step =====================================
        ull C[4];
#pragma unroll
        for (int p = 0; p < 4; p++) {
            float ulo, uhi; UNPACK2(ulo, uhi, U[p]);
            ull d0; PACK2(d0, ulo, ulo);
            ull d1; PACK2(d1, uhi, uhi);
            const int i0 = 2 * p, i1 = 2 * p + 1;
            if (p == 0) {
#pragma unroll
                for (int j = 0; j < 4; j++) {
                    MUL2(C[j], M[i0][j], d0);
                    FMA2(C[j], M[i1][j], d1, C[j]);
                }
            } else {
#pragma unroll
                for (int j = 0; j < 4; j++) {
                    FMA2(C[j], M[i0][j], d0, C[j]);
                    FMA2(C[j], M[i1][j], d1, C[j]);
                }
            }
        }
        // reduce over a-dim: masks 8 then 4
        {
            ull r;
            r = __shfl_xor_sync(FULL, C[2], 8); ADD2(C[0], C[0], r);
            r = __shfl_xor_sync(FULL, C[3], 8); ADD2(C[1], C[1], r);
            r = __shfl_xor_sync(FULL, C[1], 4); ADD2(C[0], C[0], r);
        }
        // v update
        {
            ull t; FMA2(t, v_own, C[0], EPS2);
            float tl, th; UNPACK2(tl, th, t);
            float rl, rh; RCPA(rl, tl); RCPA(rh, th);
            ull rp; PACK2(rp, rl, rh);
            MUL2(v_own, v_own, rp);
        }
        // v allgather over a-dim: V[j] = v-pair for actual pair a^j
        V[0] = v_own;
        V[1] = __shfl_xor_sync(FULL, v_own, 4);
        V[2] = __shfl_xor_sync(FULL, v_own, 8);
        V[3] = __shfl_xor_sync(FULL, v_own, 12);
    }

    // ---- Epilogue: out[i][j] = u_i * M0[i][j] * v_j ----
#pragma unroll
    for (int p = 0; p < 4; p++) {
        float ulo, uhi; UNPACK2(ulo, uhi, U[p]);
#pragma unroll
        for (int e = 0; e < 2; e++) {
            const int i2  = 2 * p + e;
            const int row = 8 * a + 2 * (b ^ p) + e;
            ull ud; { float uv = e ? uhi : ulo; PACK2(ud, uv, uv); }
#pragma unroll
            for (int q = 0; q < 2; q++) {
                ull o0, o1;
                MUL2(o0, M[i2][2 * q],     V[2 * q]);
                MUL2(o0, o0, ud);
                MUL2(o1, M[i2][2 * q + 1], V[2 * q + 1]);
                MUL2(o1, o1, ud);
                const ull xy = al ? o1 : o0;
                const ull zw = al ? o0 : o1;
                float4 t;
                UNPACK2(t.x, t.y, xy);
                UNPACK2(t.z, t.w, zw);
                dst[row * 8 + 2 * b + (ah ^ q)] = t;
            }
        }
    }
}

extern "C" void kernel_launch(void* const* d_in, const int* in_sizes, int n_in,
                              void* d_out, int out_size) {
    const float* H   = (const float*)d_in[0];
    float*       out = (float*)d_out;
    const int nmat   = in_sizes[0] / 1024;               // 32*32 per matrix
    const int mpb    = 2 * WPB;                          // matrices per block
    const int blocks = (nmat + mpb - 1) / mpb;
    sinkhorn_kernel<<<blocks, WPB * 32>>>(H, out, nmat);
}